// round 16
// baseline (speedup 1.0000x reference)
#include <cuda_runtime.h>
#include <cuda_fp16.h>
#include <cstdint>

#define D        128
#define NTEST    4096
#define NTRAIN   16384
#define TM       256
#define TN       128
#define NTILES   128                 // n-chunks per m-tile
#define NJOBS    (16 * NTILES)       // 2048
#define NTHREADS 256                 // 8 warps: 4m x 2n, warp tile 64x64
#define NRING    4                   // B ring depth

// ---------------- device scratch (zero-initialized at module load) ----------------
__device__ double g_colsum[D];
__device__ double g_colsumsq[D];
__device__ unsigned g_cnt;
__device__ float  g_inv_bw[D];
__device__ float  g_Z;
__device__ __half g_Ah[NTEST * D];
__device__ __half g_Bh[NTRAIN * D];
__device__ float  g_tnorm[NTEST];
__device__ float  g_trnorm[NTRAIN];

// ---------------- helpers ----------------
__device__ __forceinline__ uint32_t smem_u32(const void* p) {
    uint32_t a;
    asm("{ .reg .u64 t; cvta.to.shared.u64 t, %1; cvt.u32.u64 %0, t; }" : "=r"(a) : "l"(p));
    return a;
}
__device__ __forceinline__ void cp16s(uint32_t dst, const void* src) {
    asm volatile("cp.async.cg.shared.global [%0], [%1], 16;" :: "r"(dst), "l"(src));
}
__device__ __forceinline__ float ex2(float x) {
    float r; asm("ex2.approx.ftz.f32 %0, %1;" : "=f"(r) : "f"(x)); return r;
}
__device__ __forceinline__ void ldsm_x4(uint32_t (&r)[4], uint32_t addr) {
    asm volatile("ldmatrix.sync.aligned.m8n8.x4.shared.b16 {%0,%1,%2,%3}, [%4];"
                 : "=r"(r[0]), "=r"(r[1]), "=r"(r[2]), "=r"(r[3]) : "r"(addr));
}
__device__ __forceinline__ void mma16816(float (&d)[4], const uint32_t (&a)[4],
                                         uint32_t b0, uint32_t b1) {
    asm volatile("mma.sync.aligned.m16n8k16.row.col.f32.f16.f16.f32 "
                 "{%0,%1,%2,%3}, {%4,%5,%6,%7}, {%8,%9}, {%0,%1,%2,%3};"
                 : "+f"(d[0]), "+f"(d[1]), "+f"(d[2]), "+f"(d[3])
                 : "r"(a[0]), "r"(a[1]), "r"(a[2]), "r"(a[3]), "r"(b0), "r"(b1));
}
__device__ __forceinline__ void mbar_init(uint32_t a, uint32_t n) {
    asm volatile("mbarrier.init.shared.b64 [%0], %1;" :: "r"(a), "r"(n) : "memory");
}
__device__ __forceinline__ void mbar_arrive(uint32_t a) {
    asm volatile("mbarrier.arrive.shared.b64 _, [%0];" :: "r"(a) : "memory");
}
__device__ __forceinline__ void mbar_wait(uint32_t a, uint32_t ph) {
    uint32_t done;
    asm volatile("{ .reg .pred p; mbarrier.try_wait.parity.shared.b64 p, [%1], %2; selp.b32 %0,1,0,p; }"
                 : "=r"(done) : "r"(a), "r"(ph) : "memory");
    while (!done) {
        asm volatile("{ .reg .pred p; mbarrier.try_wait.parity.shared.b64 p, [%1], %2, 0x989680; selp.b32 %0,1,0,p; }"
                     : "=r"(done) : "r"(a), "r"(ph) : "memory");
    }
}
// .noinc: cp.async completion decrements the init count (default form pre-increments).
__device__ __forceinline__ void cpasync_mbar_arrive(uint32_t a) {
    asm volatile("cp.async.mbarrier.arrive.noinc.shared.b64 [%0];" :: "r"(a) : "memory");
}

// ---------------- SMEM layout (per block, 1 block/SM) ----------------
#define SM_A     0
#define SM_B     65536
#define SM_TRN   196608
#define SM_MBAR  200704
#define SM_TOTAL 200768

// -------- launch 1: column stats (max-parallel, fp32 partials) + last-block finalize --------
// 1024 blocks x 256 threads; block covers 16 rows; warp covers 2 rows (2 loads/thread).
__global__ void k_stats(const float* __restrict__ train, float* __restrict__ out) {
    const int warp = threadIdx.x >> 5, lane = threadIdx.x & 31;
    const int c4 = lane * 4;
    const int rbase = blockIdx.x * 16 + warp * 2;

    float4 v0 = *(const float4*)(train + (size_t)rbase * D + c4);
    float4 v1 = *(const float4*)(train + (size_t)(rbase + 1) * D + c4);
    float s[4], s2[4];
    s[0] = v0.x + v1.x; s2[0] = v0.x * v0.x + v1.x * v1.x;
    s[1] = v0.y + v1.y; s2[1] = v0.y * v0.y + v1.y * v1.y;
    s[2] = v0.z + v1.z; s2[2] = v0.z * v0.z + v1.z * v1.z;
    s[3] = v0.w + v1.w; s2[3] = v0.w * v0.w + v1.w * v1.w;

    __shared__ float sh[2][8][D];
#pragma unroll
    for (int j = 0; j < 4; ++j) { sh[0][warp][c4 + j] = s[j]; sh[1][warp][c4 + j] = s2[j]; }
    __syncthreads();
    if (threadIdx.x < D) {
        const int c = threadIdx.x;
        double a = 0, b2 = 0;
#pragma unroll
        for (int w = 0; w < 8; ++w) { a += (double)sh[0][w][c]; b2 += (double)sh[1][w][c]; }
        atomicAdd(&g_colsum[c], a);
        atomicAdd(&g_colsumsq[c], b2);
    }
    __threadfence();
    __shared__ int last;
    if (threadIdx.x == 0) last = (atomicAdd(&g_cnt, 1u) == (unsigned)(gridDim.x - 1));
    __syncthreads();
    if (!last) return;

    // ---- finalize (one block; all 256 threads participate in barriers) ----
    __shared__ double red[D];
    const int c = threadIdx.x;
    if (c < D) {
        const double n = (double)NTRAIN;
        double mean = g_colsum[c] / n;
        double var  = (g_colsumsq[c] - n * mean * mean) / (n - 1.0);
        double sd   = sqrt(fmax(var, 0.0));
        sd = fmax(sd, 0.01);
        double bw = 1.06 * sd * exp(-log(n) / (4.0 + (double)D));
        bw = fmin(bw, 0.49);
        g_inv_bw[c] = (float)(1.0 / bw);
        red[c] = log(bw);
    }
    __syncthreads();
    for (int off = 64; off; off >>= 1) {
        if (c < off) red[c] += red[c + off];
        __syncthreads();
    }
    if (c == 0) {
        double Z = 0.5 * (double)D * log(2.0 * 3.14159265358979323846) + red[0] + log((double)NTRAIN);
        g_Z = (float)Z;
        g_cnt = 0u;                       // re-arm for next graph replay
    }
    if (c < D) { g_colsum[c] = 0.0; g_colsumsq[c] = 0.0; }
    for (int i = c; i < NTEST; i += 256) out[i] = 0.f;
}

// -------- launch 2: scale, fp16 quantize, norms --------
__global__ void k_split(const float* __restrict__ test, const float* __restrict__ train) {
    const int lane = threadIdx.x & 31;
    const int r = blockIdx.x * 8 + (threadIdx.x >> 5);
    const float* src; __half* d1; float* nrm; int rr = r;
    if (r < NTEST) { src = test;  d1 = g_Ah; nrm = g_tnorm; }
    else { rr = r - NTEST; src = train; d1 = g_Bh; nrm = g_trnorm; }

    const int c4 = lane * 4;
    float4 v = *(const float4*)(src + (size_t)rr * D + c4);
    float4 w = *(const float4*)(g_inv_bw + c4);
    v.x *= w.x; v.y *= w.y; v.z *= w.z; v.w *= w.w;

    __half2 p1a = __floats2half2_rn(v.x, v.y);
    __half2 p1b = __floats2half2_rn(v.z, v.w);
    *(__half2*)(d1 + (size_t)rr * D + c4)     = p1a;
    *(__half2*)(d1 + (size_t)rr * D + c4 + 2) = p1b;

    float s = v.x * v.x + v.y * v.y + v.z * v.z + v.w * v.w;
#pragma unroll
    for (int off = 16; off; off >>= 1) s += __shfl_xor_sync(0xffffffffu, s, off);
    if (lane == 0) nrm[rr] = s;
}

// -------- launch 3: persistent 1-limb fp16 HMMA GEMM, ring-4 mbarrier pipeline --------
extern __shared__ char smem[];

__global__ void __launch_bounds__(NTHREADS, 1) k_main(float* __restrict__ out) {
    const uint32_t sb = smem_u32(smem);
    const int tid = threadIdx.x, lane = tid & 31, wid = tid >> 5;
    const int wm = wid >> 1, wn = wid & 1;   // 4m x 2n; warp tile 64x64
    const int qr = lane >> 2, qc = lane & 3;

    uint32_t mb_full[NRING], mb_cons[NRING];
#pragma unroll
    for (int i = 0; i < NRING; ++i) {
        mb_full[i] = sb + SM_MBAR + i * 8;
        mb_cons[i] = sb + SM_MBAR + 32 + i * 8;
    }
    if (tid == 0) {
#pragma unroll
        for (int i = 0; i < NRING; ++i) {
            mbar_init(mb_full[i], NTHREADS);
            mbar_init(mb_cons[i], NTHREADS);
        }
    }
    __syncthreads();

    const int G = gridDim.x, b = blockIdx.x;
    const int per = NJOBS / G, rem = NJOBS % G;
    const int lo = b * per + min(b, rem);
    const int nloc = per + (b < rem ? 1 : 0);
    if (nloc <= 0) return;

    const float Zf = g_Z;
    const float c0v  = -0.72134752f / Zf;  // -0.5*log2(e)/Z
    const float m2c0 = -2.f * c0v;         // coefficient of d
    const float c1v  = -1.44269504f;       // -log2(e)

    int rowid[8];
#pragma unroll
    for (int i = 0; i < 8; ++i) rowid[i] = wm * 64 + (i >> 1) * 16 + (i & 1) * 8 + qr;

    const int arow = wm * 64 + (lane & 15);
    const int akg  = lane >> 4;
    const int nofs = (lane & 7) + ((lane >> 4) << 3);
    const int bkg  = (lane >> 3) & 1;

    auto loadA = [&](int mbase) {
        for (int i = tid; i < 4096; i += NTHREADS) {
            int r = i >> 4, g = i & 15;
            const __half* src = g_Ah + (size_t)(mbase + r) * D + g * 8;
            cp16s(sb + SM_A + (uint32_t)(r * 256 + ((g ^ (r & 7)) << 4)), src);
        }
        asm volatile("cp.async.commit_group;" ::: "memory");
        asm volatile("cp.async.wait_all;" ::: "memory");
        __syncthreads();
    };
    auto loadB = [&](int jobidx, int buf) {
        const int nbase = (jobidx & (NTILES - 1)) * TN;
        for (int i = tid; i < 2048; i += NTHREADS) {
            int r = i >> 4, g = i & 15;
            const __half* src = g_Bh + (size_t)(nbase + r) * D + g * 8;
            cp16s(sb + SM_B + buf * 32768 +
                      (uint32_t)(r * 256 + ((g ^ (r & 7)) << 4)), src);
        }
        if (tid < 32)
            cp16s(sb + SM_TRN + (jobidx & 7) * 512 + tid * 16, g_trnorm + nbase + tid * 4);
        cpasync_mbar_arrive(mb_full[buf]);
    };

    float acc[4][8][4];
    float accR[8];
#pragma unroll
    for (int i = 0; i < 8; ++i) accR[i] = 0.f;
    float tnv[8];   // c0 * tnorm[row]
    int fph[NRING] = {0, 0, 0, 0}, cph[NRING] = {0, 0, 0, 0};

    int cur_m = lo >> 7;   // / NTILES
    loadA(cur_m * TM);
#pragma unroll
    for (int k = 0; k < NRING; ++k)
        if (k < nloc) loadB(lo + k, k);
#pragma unroll
    for (int i = 0; i < 8; ++i) tnv[i] = c0v * g_tnorm[cur_m * TM + rowid[i]];

    for (int t = 0; t < nloc; ++t) {
        const int job = lo + t;
        const int mt = job >> 7;
        const int buf = t & (NRING - 1);

        if (mt != cur_m) {
#pragma unroll
            for (int i = 0; i < 8; ++i) {
                float s = accR[i];
                s += __shfl_xor_sync(0xffffffffu, s, 1);
                s += __shfl_xor_sync(0xffffffffu, s, 2);
                if (qc == 0) atomicAdd(&out[cur_m * TM + rowid[i]], s);
                accR[i] = 0.f;
            }
            __syncthreads();
            loadA(mt * TM);
            cur_m = mt;
#pragma unroll
            for (int i = 0; i < 8; ++i) tnv[i] = c0v * g_tnorm[cur_m * TM + rowid[i]];
        }

        mbar_wait(mb_full[buf], fph[buf] & 1);
        fph[buf]++;

#pragma unroll
        for (int im = 0; im < 4; ++im)
#pragma unroll
            for (int jn = 0; jn < 8; ++jn)
#pragma unroll
                for (int e = 0; e < 4; ++e) acc[im][jn][e] = 0.f;

        const uint32_t A0 = sb + SM_A;
        const uint32_t B0 = sb + SM_B + buf * 32768;

#pragma unroll
        for (int ks = 0; ks < 8; ++ks) {
            const int ga = ks * 2 + akg, gb = ks * 2 + bkg;
            uint32_t a[4][4];
#pragma unroll
            for (int im = 0; im < 4; ++im) {
                int row = arow + im * 16;
                ldsm_x4(a[im], A0 + (uint32_t)(row * 256 + ((ga ^ (row & 7)) << 4)));
            }
            uint32_t bf[4][4];
#pragma unroll
            for (int j = 0; j < 4; ++j) {
                int row = wn * 64 + j * 16 + nofs;
                ldsm_x4(bf[j], B0 + (uint32_t)(row * 256 + ((gb ^ (row & 7)) << 4)));
            }
#pragma unroll
            for (int im = 0; im < 4; ++im)
#pragma unroll
                for (int jn = 0; jn < 8; ++jn)
                    mma16816(acc[im][jn], a[im],
                             bf[jn >> 1][(jn & 1) * 2], bf[jn >> 1][(jn & 1) * 2 + 1]);
        }

        mbar_arrive(mb_cons[buf]);     // this warp done reading B(t)

        // epilogue(t): arg = d*(-2c0) + (c0*trn + c1) + c0*tn; exp2
        const float* trn = (const float*)(smem + SM_TRN + (job & 7) * 512) + wn * 64;
        float u[16];
#pragma unroll
        for (int j = 0; j < 8; ++j) {
            u[2 * j]     = fmaf(c0v, trn[j * 8 + qc * 2],     c1v);
            u[2 * j + 1] = fmaf(c0v, trn[j * 8 + qc * 2 + 1], c1v);
        }
#pragma unroll
        for (int im = 0; im < 4; ++im)
#pragma unroll
            for (int jn = 0; jn < 8; ++jn)
#pragma unroll
                for (int e = 0; e < 4; ++e) {
                    int h = e >> 1;
                    float arg = fmaf(acc[im][jn][e], m2c0, u[2 * jn + (e & 1)]) + tnv[im * 2 + h];
                    accR[im * 2 + h] += ex2(arg);
                }

        if (t + NRING < nloc) {
            mbar_wait(mb_cons[buf], cph[buf] & 1);
            cph[buf]++;
            loadB(lo + t + NRING, buf);
        }
    }

    // final flush
#pragma unroll
    for (int i = 0; i < 8; ++i) {
        float s = accR[i];
        s += __shfl_xor_sync(0xffffffffu, s, 1);
        s += __shfl_xor_sync(0xffffffffu, s, 2);
        if (qc == 0) atomicAdd(&out[cur_m * TM + rowid[i]], s);
    }
}

extern "C" void kernel_launch(void* const* d_in, const int* in_sizes, int n_in,
                              void* d_out, int out_size) {
    const float* test  = (const float*)d_in[0];
    const float* train = (const float*)d_in[1];
    float* out = (float*)d_out;
    (void)in_sizes; (void)n_in; (void)out_size;

    int dev = 0;
    cudaGetDevice(&dev);
    int smc = 148;
    cudaDeviceGetAttribute(&smc, cudaDevAttrMultiProcessorCount, dev);

    cudaFuncSetAttribute(k_main, cudaFuncAttributeMaxDynamicSharedMemorySize, SM_TOTAL);

    k_stats<<<NTRAIN / 16, 256>>>(train, out);
    k_split<<<(NTEST + NTRAIN) / 8, 256>>>(test, train);
    k_main<<<smc, NTHREADS, SM_TOTAL>>>(out);
}

// round 17
// speedup vs baseline: 1.8099x; 1.8099x over previous
#include <cuda_runtime.h>
#include <cuda_fp16.h>
#include <cstdint>

#define D        128
#define NTEST    4096
#define NTRAIN   16384
#define TM       256
#define TN       128
#define NTILES   128                 // n-chunks per m-tile
#define NJOBS    (16 * NTILES)       // 2048
#define NTHREADS 256                 // 8 warps: 4m x 2n, warp tile 64x64
#define NRING    4                   // B ring depth
#define NREP     8                   // stats replica accumulators

// ---------------- device scratch (zero-initialized at module load) ----------------
__device__ float  g_colsum32[NREP][D];
__device__ float  g_colsumsq32[NREP][D];
__device__ unsigned g_cnt;
__device__ float  g_inv_bw[D];
__device__ float  g_Z;
__device__ __half g_Ah[NTEST * D];
__device__ __half g_Bh[NTRAIN * D];
__device__ float  g_tnorm[NTEST];
__device__ float  g_trnorm[NTRAIN];

// ---------------- helpers ----------------
__device__ __forceinline__ uint32_t smem_u32(const void* p) {
    uint32_t a;
    asm("{ .reg .u64 t; cvta.to.shared.u64 t, %1; cvt.u32.u64 %0, t; }" : "=r"(a) : "l"(p));
    return a;
}
__device__ __forceinline__ void cp16s(uint32_t dst, const void* src) {
    asm volatile("cp.async.cg.shared.global [%0], [%1], 16;" :: "r"(dst), "l"(src));
}
__device__ __forceinline__ float ex2(float x) {
    float r; asm("ex2.approx.ftz.f32 %0, %1;" : "=f"(r) : "f"(x)); return r;
}
__device__ __forceinline__ void ldsm_x4(uint32_t (&r)[4], uint32_t addr) {
    asm volatile("ldmatrix.sync.aligned.m8n8.x4.shared.b16 {%0,%1,%2,%3}, [%4];"
                 : "=r"(r[0]), "=r"(r[1]), "=r"(r[2]), "=r"(r[3]) : "r"(addr));
}
__device__ __forceinline__ void mma16816(float (&d)[4], const uint32_t (&a)[4],
                                         uint32_t b0, uint32_t b1) {
    asm volatile("mma.sync.aligned.m16n8k16.row.col.f32.f16.f16.f32 "
                 "{%0,%1,%2,%3}, {%4,%5,%6,%7}, {%8,%9}, {%0,%1,%2,%3};"
                 : "+f"(d[0]), "+f"(d[1]), "+f"(d[2]), "+f"(d[3])
                 : "r"(a[0]), "r"(a[1]), "r"(a[2]), "r"(a[3]), "r"(b0), "r"(b1));
}
__device__ __forceinline__ void mbar_init(uint32_t a, uint32_t n) {
    asm volatile("mbarrier.init.shared.b64 [%0], %1;" :: "r"(a), "r"(n) : "memory");
}
__device__ __forceinline__ void mbar_arrive(uint32_t a) {
    asm volatile("mbarrier.arrive.shared.b64 _, [%0];" :: "r"(a) : "memory");
}
__device__ __forceinline__ void mbar_wait(uint32_t a, uint32_t ph) {
    uint32_t done;
    asm volatile("{ .reg .pred p; mbarrier.try_wait.parity.shared.b64 p, [%1], %2; selp.b32 %0,1,0,p; }"
                 : "=r"(done) : "r"(a), "r"(ph) : "memory");
    while (!done) {
        asm volatile("{ .reg .pred p; mbarrier.try_wait.parity.shared.b64 p, [%1], %2, 0x989680; selp.b32 %0,1,0,p; }"
                     : "=r"(done) : "r"(a), "r"(ph) : "memory");
    }
}
// .noinc: cp.async completion decrements the init count (default form pre-increments).
__device__ __forceinline__ void cpasync_mbar_arrive(uint32_t a) {
    asm volatile("cp.async.mbarrier.arrive.noinc.shared.b64 [%0];" :: "r"(a) : "memory");
}

// ---------------- SMEM layout (per block, 1 block/SM) ----------------
#define SM_A     0
#define SM_B     65536
#define SM_TRN   196608
#define SM_MBAR  200704
#define SM_TOTAL 200768

// -------- launch 1: column stats (1024 blocks, fp32 replica atomics) + last-block finalize --------
__global__ void k_stats(const float* __restrict__ train, float* __restrict__ out) {
    const int warp = threadIdx.x >> 5, lane = threadIdx.x & 31;
    const int c4 = lane * 4;
    const int rbase = blockIdx.x * 16 + warp * 2;

    float4 v0 = *(const float4*)(train + (size_t)rbase * D + c4);
    float4 v1 = *(const float4*)(train + (size_t)(rbase + 1) * D + c4);
    float s[4], s2[4];
    s[0] = v0.x + v1.x; s2[0] = v0.x * v0.x + v1.x * v1.x;
    s[1] = v0.y + v1.y; s2[1] = v0.y * v0.y + v1.y * v1.y;
    s[2] = v0.z + v1.z; s2[2] = v0.z * v0.z + v1.z * v1.z;
    s[3] = v0.w + v1.w; s2[3] = v0.w * v0.w + v1.w * v1.w;

    __shared__ float sh[2][8][D];
#pragma unroll
    for (int j = 0; j < 4; ++j) { sh[0][warp][c4 + j] = s[j]; sh[1][warp][c4 + j] = s2[j]; }
    __syncthreads();
    const int rep = blockIdx.x & (NREP - 1);
    if (threadIdx.x < D) {
        const int c = threadIdx.x;
        float a = 0.f, b2 = 0.f;
#pragma unroll
        for (int w = 0; w < 8; ++w) { a += sh[0][w][c]; b2 += sh[1][w][c]; }
        atomicAdd(&g_colsum32[rep][c], a);     // fp32 RED, 128 writers/address
        atomicAdd(&g_colsumsq32[rep][c], b2);
    }
    __threadfence();
    __shared__ int last;
    if (threadIdx.x == 0) last = (atomicAdd(&g_cnt, 1u) == (unsigned)(gridDim.x - 1));
    __syncthreads();
    if (!last) return;

    // ---- finalize (one block; all 256 threads participate in barriers) ----
    __shared__ double red[D];
    const int c = threadIdx.x;
    if (c < D) {
        double csum = 0.0, csq = 0.0;
#pragma unroll
        for (int r = 0; r < NREP; ++r) {
            csum += (double)g_colsum32[r][c];
            csq  += (double)g_colsumsq32[r][c];
            g_colsum32[r][c] = 0.f;            // re-arm for next graph replay
            g_colsumsq32[r][c] = 0.f;
        }
        const double n = (double)NTRAIN;
        double mean = csum / n;
        double var  = (csq - n * mean * mean) / (n - 1.0);
        double sd   = sqrt(fmax(var, 0.0));
        sd = fmax(sd, 0.01);
        double bw = 1.06 * sd * exp(-log(n) / (4.0 + (double)D));
        bw = fmin(bw, 0.49);
        g_inv_bw[c] = (float)(1.0 / bw);
        red[c] = log(bw);
    }
    __syncthreads();
    for (int off = 64; off; off >>= 1) {
        if (c < off) red[c] += red[c + off];
        __syncthreads();
    }
    if (c == 0) {
        double Z = 0.5 * (double)D * log(2.0 * 3.14159265358979323846) + red[0] + log((double)NTRAIN);
        g_Z = (float)Z;
        g_cnt = 0u;
    }
    for (int i = c; i < NTEST; i += 256) out[i] = 0.f;
}

// -------- launch 2: scale, fp16 quantize, norms --------
__global__ void k_split(const float* __restrict__ test, const float* __restrict__ train) {
    const int lane = threadIdx.x & 31;
    const int r = blockIdx.x * 8 + (threadIdx.x >> 5);
    const float* src; __half* d1; float* nrm; int rr = r;
    if (r < NTEST) { src = test;  d1 = g_Ah; nrm = g_tnorm; }
    else { rr = r - NTEST; src = train; d1 = g_Bh; nrm = g_trnorm; }

    const int c4 = lane * 4;
    float4 v = *(const float4*)(src + (size_t)rr * D + c4);
    float4 w = *(const float4*)(g_inv_bw + c4);
    v.x *= w.x; v.y *= w.y; v.z *= w.z; v.w *= w.w;

    __half2 p1a = __floats2half2_rn(v.x, v.y);
    __half2 p1b = __floats2half2_rn(v.z, v.w);
    *(__half2*)(d1 + (size_t)rr * D + c4)     = p1a;
    *(__half2*)(d1 + (size_t)rr * D + c4 + 2) = p1b;

    float s = v.x * v.x + v.y * v.y + v.z * v.z + v.w * v.w;
#pragma unroll
    for (int off = 16; off; off >>= 1) s += __shfl_xor_sync(0xffffffffu, s, off);
    if (lane == 0) nrm[rr] = s;
}

// -------- launch 3: persistent 1-limb fp16 HMMA GEMM, ring-4 mbarrier pipeline --------
extern __shared__ char smem[];

__global__ void __launch_bounds__(NTHREADS, 1) k_main(float* __restrict__ out) {
    const uint32_t sb = smem_u32(smem);
    const int tid = threadIdx.x, lane = tid & 31, wid = tid >> 5;
    const int wm = wid >> 1, wn = wid & 1;   // 4m x 2n; warp tile 64x64
    const int qr = lane >> 2, qc = lane & 3;

    uint32_t mb_full[NRING], mb_cons[NRING];
#pragma unroll
    for (int i = 0; i < NRING; ++i) {
        mb_full[i] = sb + SM_MBAR + i * 8;
        mb_cons[i] = sb + SM_MBAR + 32 + i * 8;
    }
    if (tid == 0) {
#pragma unroll
        for (int i = 0; i < NRING; ++i) {
            mbar_init(mb_full[i], NTHREADS);
            mbar_init(mb_cons[i], NTHREADS);
        }
    }
    __syncthreads();

    const int G = gridDim.x, b = blockIdx.x;
    const int per = NJOBS / G, rem = NJOBS % G;
    const int lo = b * per + min(b, rem);
    const int nloc = per + (b < rem ? 1 : 0);
    if (nloc <= 0) return;

    const float Zf = g_Z;
    const float c0v  = -0.72134752f / Zf;  // -0.5*log2(e)/Z
    const float m2c0 = -2.f * c0v;         // coefficient of d
    const float c1v  = -1.44269504f;       // -log2(e)

    int rowid[8];
#pragma unroll
    for (int i = 0; i < 8; ++i) rowid[i] = wm * 64 + (i >> 1) * 16 + (i & 1) * 8 + qr;

    const int arow = wm * 64 + (lane & 15);
    const int akg  = lane >> 4;
    const int nofs = (lane & 7) + ((lane >> 4) << 3);
    const int bkg  = (lane >> 3) & 1;

    auto loadA = [&](int mbase) {
        for (int i = tid; i < 4096; i += NTHREADS) {
            int r = i >> 4, g = i & 15;
            const __half* src = g_Ah + (size_t)(mbase + r) * D + g * 8;
            cp16s(sb + SM_A + (uint32_t)(r * 256 + ((g ^ (r & 7)) << 4)), src);
        }
        asm volatile("cp.async.commit_group;" ::: "memory");
        asm volatile("cp.async.wait_all;" ::: "memory");
        __syncthreads();
    };
    auto loadB = [&](int jobidx, int buf) {
        const int nbase = (jobidx & (NTILES - 1)) * TN;
        for (int i = tid; i < 2048; i += NTHREADS) {
            int r = i >> 4, g = i & 15;
            const __half* src = g_Bh + (size_t)(nbase + r) * D + g * 8;
            cp16s(sb + SM_B + buf * 32768 +
                      (uint32_t)(r * 256 + ((g ^ (r & 7)) << 4)), src);
        }
        if (tid < 32)
            cp16s(sb + SM_TRN + (jobidx & 7) * 512 + tid * 16, g_trnorm + nbase + tid * 4);
        cpasync_mbar_arrive(mb_full[buf]);
    };

    float acc[4][8][4];
    float accR[8];
#pragma unroll
    for (int i = 0; i < 8; ++i) accR[i] = 0.f;
    float tnv[8];   // c0 * tnorm[row]
    int fph[NRING] = {0, 0, 0, 0}, cph[NRING] = {0, 0, 0, 0};

    int cur_m = lo >> 7;   // / NTILES
    loadA(cur_m * TM);
#pragma unroll
    for (int k = 0; k < NRING; ++k)
        if (k < nloc) loadB(lo + k, k);
#pragma unroll
    for (int i = 0; i < 8; ++i) tnv[i] = c0v * g_tnorm[cur_m * TM + rowid[i]];

    for (int t = 0; t < nloc; ++t) {
        const int job = lo + t;
        const int mt = job >> 7;
        const int buf = t & (NRING - 1);

        if (mt != cur_m) {
#pragma unroll
            for (int i = 0; i < 8; ++i) {
                float s = accR[i];
                s += __shfl_xor_sync(0xffffffffu, s, 1);
                s += __shfl_xor_sync(0xffffffffu, s, 2);
                if (qc == 0) atomicAdd(&out[cur_m * TM + rowid[i]], s);
                accR[i] = 0.f;
            }
            __syncthreads();
            loadA(mt * TM);
            cur_m = mt;
#pragma unroll
            for (int i = 0; i < 8; ++i) tnv[i] = c0v * g_tnorm[cur_m * TM + rowid[i]];
        }

        mbar_wait(mb_full[buf], fph[buf] & 1);
        fph[buf]++;

#pragma unroll
        for (int im = 0; im < 4; ++im)
#pragma unroll
            for (int jn = 0; jn < 8; ++jn)
#pragma unroll
                for (int e = 0; e < 4; ++e) acc[im][jn][e] = 0.f;

        const uint32_t A0 = sb + SM_A;
        const uint32_t B0 = sb + SM_B + buf * 32768;

#pragma unroll
        for (int ks = 0; ks < 8; ++ks) {
            const int ga = ks * 2 + akg, gb = ks * 2 + bkg;
            uint32_t a[4][4];
#pragma unroll
            for (int im = 0; im < 4; ++im) {
                int row = arow + im * 16;
                ldsm_x4(a[im], A0 + (uint32_t)(row * 256 + ((ga ^ (row & 7)) << 4)));
            }
            uint32_t bf[4][4];
#pragma unroll
            for (int j = 0; j < 4; ++j) {
                int row = wn * 64 + j * 16 + nofs;
                ldsm_x4(bf[j], B0 + (uint32_t)(row * 256 + ((gb ^ (row & 7)) << 4)));
            }
#pragma unroll
            for (int im = 0; im < 4; ++im)
#pragma unroll
                for (int jn = 0; jn < 8; ++jn)
                    mma16816(acc[im][jn], a[im],
                             bf[jn >> 1][(jn & 1) * 2], bf[jn >> 1][(jn & 1) * 2 + 1]);
        }

        mbar_arrive(mb_cons[buf]);     // this warp done reading B(t)

        // epilogue(t): arg = d*(-2c0) + (c0*trn + c1) + c0*tn; exp2
        const float* trn = (const float*)(smem + SM_TRN + (job & 7) * 512) + wn * 64;
        float u[16];
#pragma unroll
        for (int j = 0; j < 8; ++j) {
            u[2 * j]     = fmaf(c0v, trn[j * 8 + qc * 2],     c1v);
            u[2 * j + 1] = fmaf(c0v, trn[j * 8 + qc * 2 + 1], c1v);
        }
#pragma unroll
        for (int im = 0; im < 4; ++im)
#pragma unroll
            for (int jn = 0; jn < 8; ++jn)
#pragma unroll
                for (int e = 0; e < 4; ++e) {
                    int h = e >> 1;
                    float arg = fmaf(acc[im][jn][e], m2c0, u[2 * jn + (e & 1)]) + tnv[im * 2 + h];
                    accR[im * 2 + h] += ex2(arg);
                }

        if (t + NRING < nloc) {
            mbar_wait(mb_cons[buf], cph[buf] & 1);
            cph[buf]++;
            loadB(lo + t + NRING, buf);
        }
    }

    // final flush
#pragma unroll
    for (int i = 0; i < 8; ++i) {
        float s = accR[i];
        s += __shfl_xor_sync(0xffffffffu, s, 1);
        s += __shfl_xor_sync(0xffffffffu, s, 2);
        if (qc == 0) atomicAdd(&out[cur_m * TM + rowid[i]], s);
    }
}

extern "C" void kernel_launch(void* const* d_in, const int* in_sizes, int n_in,
                              void* d_out, int out_size) {
    const float* test  = (const float*)d_in[0];
    const float* train = (const float*)d_in[1];
    float* out = (float*)d_out;
    (void)in_sizes; (void)n_in; (void)out_size;

    int dev = 0;
    cudaGetDevice(&dev);
    int smc = 148;
    cudaDeviceGetAttribute(&smc, cudaDevAttrMultiProcessorCount, dev);

    cudaFuncSetAttribute(k_main, cudaFuncAttributeMaxDynamicSharedMemorySize, SM_TOTAL);

    k_stats<<<NTRAIN / 16, 256>>>(train, out);
    k_split<<<(NTEST + NTRAIN) / 8, 256>>>(test, train);
    k_main<<<smc, NTHREADS, SM_TOTAL>>>(out);
}